// round 1
// baseline (speedup 1.0000x reference)
#include <cuda_runtime.h>
#include <cuda_bf16.h>
#include <math.h>

#define BATCH   16384
#define N_DENSE 13
#define N_TAB   26
#define VOCAB   1000000

// Runtime-detected index width: 1 if x_cat is int64, 0 if int32.
__device__ int g_idx_is64;

__global__ void probe_idx_kernel(const long long* __restrict__ xc) {
    if (threadIdx.x == 0 && blockIdx.x == 0) {
        int is64 = 1;
        #pragma unroll 1
        for (int i = 0; i < 64; i++) {
            unsigned long long v = (unsigned long long)xc[i];
            if (v >> 32) { is64 = 0; break; }
        }
        g_idx_is64 = is64;
    }
}

__global__ __launch_bounds__(128)
void dlrm_fused_kernel(
    const float*      __restrict__ xd,    // [B,13]
    const void*       __restrict__ xc_v,  // [B,26] int32 or int64
    const float*      __restrict__ emb,   // [26, V, 2]
    const float*      __restrict__ bw1,   // [13,3]
    const float*      __restrict__ bb1,   // [3]
    const float*      __restrict__ bw2,   // [3,2]
    const float*      __restrict__ bb2,   // [2]
    const float*      __restrict__ tw1,   // [54,4]
    const float*      __restrict__ tb1,   // [4]
    const float*      __restrict__ tw2,   // [4,2]
    const float*      __restrict__ tb2,   // [2]
    const float*      __restrict__ tw3,   // [2,1]
    const float*      __restrict__ tb3,   // [1]
    float*            __restrict__ out)   // [B,1]
{
    // ---- stage all weights in shared (broadcast LDS instead of 216 LDG/row) ----
    __shared__ float s_bw1[39], s_bb1[3], s_bw2[6], s_bb2[2];
    __shared__ float s_tw1[216], s_tb1[4], s_tw2[8], s_tb2[2], s_tw3[2], s_tb3[1];

    const int t = threadIdx.x;
    if (t < 39) s_bw1[t] = bw1[t];
    if (t < 3)  s_bb1[t] = bb1[t];
    if (t < 6)  s_bw2[t] = bw2[t];
    if (t < 2)  s_bb2[t] = bb2[t];
    for (int i = t; i < 216; i += 128) s_tw1[i] = tw1[i];
    if (t < 4)  s_tb1[t] = tb1[t];
    if (t < 8)  s_tw2[t] = tw2[t];
    if (t < 2)  s_tb2[t] = tb2[t];
    if (t < 2)  s_tw3[t] = tw3[t];
    if (t == 0) s_tb3[0] = tb3[0];
    __syncthreads();

    const int row = blockIdx.x * 128 + t;
    if (row >= BATCH) return;

    const int is64 = g_idx_is64;  // uniform branch

    // ---- issue all 26 independent embedding gathers up front (max MLP) ----
    float2 e[N_TAB];
    if (is64) {
        const long long* ci = (const long long*)xc_v + (long long)row * N_TAB;
        #pragma unroll
        for (int k = 0; k < N_TAB; k++) {
            long long idx = ci[k];
            e[k] = *reinterpret_cast<const float2*>(
                emb + ((long long)k * VOCAB + idx) * 2);
        }
    } else {
        const int* ci = (const int*)xc_v + (long long)row * N_TAB;
        #pragma unroll
        for (int k = 0; k < N_TAB; k++) {
            long long idx = (long long)ci[k];
            e[k] = *reinterpret_cast<const float2*>(
                emb + ((long long)k * VOCAB + idx) * 2);
        }
    }

    // ---- dense features ----
    float x[N_DENSE];
    #pragma unroll
    for (int i = 0; i < N_DENSE; i++) x[i] = xd[row * N_DENSE + i];

    // ---- bottom MLP: 13 -> 3 -> 2, relu ----
    float d1[3];
    #pragma unroll
    for (int h = 0; h < 3; h++) {
        float acc = s_bb1[h];
        #pragma unroll
        for (int i = 0; i < N_DENSE; i++) acc = fmaf(x[i], s_bw1[i * 3 + h], acc);
        d1[h] = fmaxf(acc, 0.0f);
    }
    float d2[2];
    #pragma unroll
    for (int o = 0; o < 2; o++) {
        float acc = s_bb2[o];
        #pragma unroll
        for (int h = 0; h < 3; h++) acc = fmaf(d1[h], s_bw2[h * 2 + o], acc);
        d2[o] = fmaxf(acc, 0.0f);
    }

    // ---- top MLP: concat([d2(2), e(52)]) -> 4 -> 2 -> 1, sigmoid ----
    float h1[4];
    #pragma unroll
    for (int o = 0; o < 4; o++) {
        float acc = s_tb1[o];
        acc = fmaf(d2[0], s_tw1[0 * 4 + o], acc);
        acc = fmaf(d2[1], s_tw1[1 * 4 + o], acc);
        #pragma unroll
        for (int k = 0; k < N_TAB; k++) {
            acc = fmaf(e[k].x, s_tw1[(2 + 2 * k) * 4 + o], acc);
            acc = fmaf(e[k].y, s_tw1[(3 + 2 * k) * 4 + o], acc);
        }
        h1[o] = fmaxf(acc, 0.0f);
    }
    float h2[2];
    #pragma unroll
    for (int o = 0; o < 2; o++) {
        float acc = s_tb2[o];
        #pragma unroll
        for (int j = 0; j < 4; j++) acc = fmaf(h1[j], s_tw2[j * 2 + o], acc);
        h2[o] = fmaxf(acc, 0.0f);
    }
    float z = s_tb3[0];
    z = fmaf(h2[0], s_tw3[0], z);
    z = fmaf(h2[1], s_tw3[1], z);

    out[row] = 1.0f / (1.0f + __expf(-z));
}

extern "C" void kernel_launch(void* const* d_in, const int* in_sizes, int n_in,
                              void* d_out, int out_size) {
    const float*     xd  = (const float*)d_in[0];
    const void*      xc  = d_in[1];
    const float*     emb = (const float*)d_in[2];
    const float*     bw1 = (const float*)d_in[3];
    const float*     bb1 = (const float*)d_in[4];
    const float*     bw2 = (const float*)d_in[5];
    const float*     bb2 = (const float*)d_in[6];
    const float*     tw1 = (const float*)d_in[7];
    const float*     tb1 = (const float*)d_in[8];
    const float*     tw2 = (const float*)d_in[9];
    const float*     tb2 = (const float*)d_in[10];
    const float*     tw3 = (const float*)d_in[11];
    const float*     tb3 = (const float*)d_in[12];
    float*           out = (float*)d_out;

    probe_idx_kernel<<<1, 32>>>((const long long*)xc);
    dlrm_fused_kernel<<<BATCH / 128, 128>>>(
        xd, xc, emb, bw1, bb1, bw2, bb2,
        tw1, tb1, tw2, tb2, tw3, tb3, out);
}